// round 3
// baseline (speedup 1.0000x reference)
#include <cuda_runtime.h>
#include <math.h>

#define T_DIM 512
#define B_DIM 1024
#define K_DIM 48
#define START_TAG 46
#define STOP_TAG 47
#define FULLMASK 0xffffffffu
#define QD 6
#define WPB 4
#define THREADS (WPB * 32)

typedef unsigned long long u64;

__device__ float g_c;   // per-step log-scale constant, computed from data

// ---------- packed f32x2 helpers (sm_103a) ----------
__device__ __forceinline__ u64 pack2(float lo, float hi) {
    u64 r; asm("mov.b64 %0, {%1, %2};" : "=l"(r) : "f"(lo), "f"(hi)); return r;
}
__device__ __forceinline__ void unpack2(u64 v, float& lo, float& hi) {
    asm("mov.b64 {%0, %1}, %2;" : "=f"(lo), "=f"(hi) : "l"(v));
}
__device__ __forceinline__ u64 fma2(u64 a, u64 b, u64 c) {
    u64 d; asm("fma.rn.f32x2 %0, %1, %2, %3;" : "=l"(d) : "l"(a), "l"(b), "l"(c)); return d;
}
__device__ __forceinline__ u64 add2(u64 a, u64 b) {
    u64 d; asm("add.rn.f32x2 %0, %1, %2;" : "=l"(d) : "l"(a), "l"(b)); return d;
}
__device__ __forceinline__ u64 mul2(u64 a, u64 b) {
    u64 d; asm("mul.rn.f32x2 %0, %1, %2;" : "=l"(d) : "l"(a), "l"(b)); return d;
}

// ---------- pre-kernel: zero out, compute scale constant c ----------
__global__ void crf_pre(const float* __restrict__ trans, float* __restrict__ out) {
    float s = 0.f;
    for (int i = threadIdx.x; i < K_DIM * K_DIM; i += 256) s += __expf(trans[i]);
#pragma unroll
    for (int off = 16; off; off >>= 1) s += __shfl_xor_sync(FULLMASK, s, off);
    __shared__ float red[8];
    if ((threadIdx.x & 31) == 0) red[threadIdx.x >> 5] = s;
    __syncthreads();
    if (threadIdx.x == 0) {
        float tot = 0.f;
#pragma unroll
        for (int i = 0; i < 8; i++) tot += red[i];
        g_c = __logf(tot / 46.0f);
        out[0] = 0.0f;
    }
}

// ---------- main: one warp per chain, linear-space recurrence ----------
__global__ __launch_bounds__(THREADS) void crf_fwd(
    const float* __restrict__ feats,      // (T, B, K)
    const float* __restrict__ trans,      // (K, K)
    const int*   __restrict__ tags,       // (B, T)
    const int*   __restrict__ lengths,    // (B,)
    float* __restrict__ out)
{
    __shared__ float trans_sh[K_DIM * K_DIM];
    __shared__ __align__(16) u64 dup[WPB][2][K_DIM];   // duplicated (p_i,p_i), double-buffered

    const int tid = threadIdx.x;
    const int warp = tid >> 5;
    const int lane = tid & 31;
    const int b = blockIdx.x * WPB + warp;
    const int j0 = lane;
    const int j1 = lane + 32;
    const bool has1 = (lane < 16);

    for (int i = tid; i < K_DIM * K_DIM; i += THREADS) trans_sh[i] = trans[i];
    __syncthreads();

    const float c = g_c;
    const float ec = __expf(-c);

    // packed scaled transition rows: E2[i] = (exp(trans[j0][i])*e^-c, exp(trans[j1][i])*e^-c)
    u64 E2[K_DIM];
#pragma unroll
    for (int i = 0; i < K_DIM; i++) {
        float e0 = __expf(trans_sh[j0 * K_DIM + i]) * ec;
        float e1 = has1 ? __expf(trans_sh[j1 * K_DIM + i]) * ec : 0.f;
        E2[i] = pack2(e0, e1);
    }

    const int len = lengths[b];
    const int stride = B_DIM * K_DIM;
    const float* fb = feats + b * K_DIM;
    const int* tagb = tags + b * T_DIM;

    // ---- t = 0: p_j = exp(feat0_j + trans[j][START]), running log-scale Mlog = 0 ----
    float p0v = __expf(fb[j0] + trans_sh[j0 * K_DIM + START_TAG]);
    float p1v = has1 ? __expf(fb[j1] + trans_sh[j1 * K_DIM + START_TAG]) : 0.f;
    u64 P = pack2(p0v, p1v);
    dup[warp][0][j0] = pack2(p0v, p0v);
    if (has1) dup[warp][0][j1] = pack2(p1v, p1v);

    const int t0tag = __ldg(&tagb[0]);
    float gold = trans_sh[t0tag * K_DIM + START_TAG] + fb[t0tag];
    float Mlog = 0.f;

    // ---- depth-QD prefetch queues (statically indexed) ----
    float pfq0[QD], pfq1[QD], emq[QD], gtq[QD];
    int tagq[QD];
    {
        int ptag = t0tag;
#pragma unroll
        for (int s = 0; s < QD; s++) {
            const int tp = s + 1;
            pfq0[s] = 0.f; pfq1[s] = 0.f; emq[s] = 0.f; gtq[s] = 0.f; tagq[s] = 0;
            if (tp < len) {
                const float* ft = fb + tp * stride;
                pfq0[s] = ft[j0];
                pfq1[s] = has1 ? ft[j1] : 0.f;
                const int tg = __ldg(&tagb[tp]);
                tagq[s] = tg;
                emq[s] = __ldg(&ft[tg]);
                gtq[s] = trans_sh[tg * K_DIM + ptag];
                ptag = tg;
            }
        }
    }
    __syncwarp();

    int t = 1;
    int blk = 0;
    while (t < len) {
        const bool do_renorm = ((blk & 1) == 0);   // every 12 steps
        blk++;
#pragma unroll
        for (int s = 0; s < QD; s++) {
            if (t < len) {
                // consume queue slot s (off critical chain)
                const u64 ef2 = pack2(__expf(pfq0[s]), __expf(pfq1[s]));
                const float g_add = gtq[s] + emq[s];

                // prefetch step t+QD into slot s
                if (t + QD < len) {
                    const float* ft = fb + (t + QD) * stride;
                    pfq0[s] = ft[j0];
                    pfq1[s] = has1 ? ft[j1] : 0.f;
                    const int tg = __ldg(&tagb[t + QD]);
                    emq[s] = __ldg(&ft[tg]);
                    gtq[s] = trans_sh[tg * K_DIM + tagq[(s + QD - 1) % QD]];
                    tagq[s] = tg;
                }

                // matvec in linear space: s_j = sum_i E2[j][i] * p_i  (broadcast LDS.128)
                const double2* bv = (const double2*)(dup[warp][s & 1]);
                u64 a0 = 0, a1 = 0, a2 = 0, a3 = 0;
#pragma unroll
                for (int k = 0; k < 12; k++) {
                    const double2 d0 = bv[2 * k];
                    const double2 d1 = bv[2 * k + 1];
                    a0 = fma2(__double_as_longlong(d0.x), E2[4 * k + 0], a0);
                    a1 = fma2(__double_as_longlong(d0.y), E2[4 * k + 1], a1);
                    a2 = fma2(__double_as_longlong(d1.x), E2[4 * k + 2], a2);
                    a3 = fma2(__double_as_longlong(d1.y), E2[4 * k + 3], a3);
                }
                const u64 s2 = add2(add2(a0, a1), add2(a2, a3));
                P = mul2(ef2, s2);

                if (s == 0 && do_renorm) {
                    float plo, phi; unpack2(P, plo, phi);
                    const float x = __shfl_sync(FULLMASK, plo, 0);   // p_0 > 0 always
                    Mlog += __logf(x);
                    const float r = __frcp_rn(x);
                    P = mul2(P, pack2(r, r));
                }

                float plo, phi; unpack2(P, plo, phi);
                u64* wb = dup[warp][(s + 1) & 1];
                wb[j0] = pack2(plo, plo);
                if (has1) wb[j1] = pack2(phi, phi);

                gold += g_add;
            }
            __syncwarp();
            t++;
        }
    }

    // ---- log_z = Mlog + c*(len-1) + log( sum_j p_j * exp(trans[STOP][j]) ) ----
    const float eS0 = __expf(trans_sh[STOP_TAG * K_DIM + j0]);
    const float eS1 = has1 ? __expf(trans_sh[STOP_TAG * K_DIM + j1]) : 0.f;
    float plo, phi; unpack2(P, plo, phi);
    float v = fmaf(plo, eS0, phi * eS1);
#pragma unroll
    for (int off = 16; off; off >>= 1) v += __shfl_xor_sync(FULLMASK, v, off);

    const int lastTag = __ldg(&tagb[len - 1]);
    gold += trans_sh[STOP_TAG * K_DIM + lastTag];

    const float log_z = Mlog + c * (float)(len - 1) + __logf(v);

    if (lane == 0) atomicAdd(out, log_z - gold);
}

extern "C" void kernel_launch(void* const* d_in, const int* in_sizes, int n_in,
                              void* d_out, int out_size) {
    const float* feats   = (const float*)d_in[0];
    const float* trans   = (const float*)d_in[1];
    const int*   tags    = (const int*)d_in[2];
    const int*   lengths = (const int*)d_in[3];
    float* out = (float*)d_out;

    crf_pre<<<1, 256>>>(trans, out);
    crf_fwd<<<B_DIM / WPB, THREADS>>>(feats, trans, tags, lengths, out);
}

// round 4
// speedup vs baseline: 2.4105x; 2.4105x over previous
#include <cuda_runtime.h>
#include <math.h>

#define T_DIM 512
#define B_DIM 1024
#define K_DIM 48
#define START_TAG 46
#define STOP_TAG 47
#define NEG_VAL -10000.0f
#define FULLMASK 0xffffffffu
#define QD 4
#define WPB 4
#define THREADS (WPB * 32)

__global__ void crf_zero(float* out) { out[0] = 0.0f; }

__global__ __launch_bounds__(THREADS) void crf_fwd(
    const float* __restrict__ feats,      // (T, B, K)
    const float* __restrict__ trans,      // (K, K)  [next, prev]
    const int*   __restrict__ tags,       // (B, T)
    const int*   __restrict__ lengths,    // (B,)
    float* __restrict__ out)
{
    __shared__ float trans_sh[K_DIM * K_DIM];
    __shared__ __align__(16) float a_sh[WPB][2][K_DIM];   // double-buffered exp(alpha-m)

    const int tid = threadIdx.x;
    const int warp = tid >> 5;
    const int lane = tid & 31;
    const int b = blockIdx.x * WPB + warp;
    const int j0 = lane;
    const int j1 = lane + 32;
    const bool has1 = (lane < 16);

    for (int i = tid; i < K_DIM * K_DIM; i += THREADS) trans_sh[i] = trans[i];
    __syncthreads();

    // E rows in scalar registers (proven 128-reg layout in R1)
    float E0[K_DIM], E1[K_DIM];
#pragma unroll
    for (int i = 0; i < K_DIM; i++) {
        E0[i] = __expf(trans_sh[j0 * K_DIM + i]);
        E1[i] = has1 ? __expf(trans_sh[j1 * K_DIM + i]) : 0.0f;
    }

    const int len = lengths[b];                 // in [1, T]
    const int stride = B_DIM * K_DIM;
    const float* fb = feats + b * K_DIM;
    const int* tagb = tags + b * T_DIM;

    // ---- t = 0 ----
    float alpha0 = fb[j0] + trans_sh[j0 * K_DIM + START_TAG];
    float alpha1 = has1 ? (fb[j1] + trans_sh[j1 * K_DIM + START_TAG]) : NEG_VAL;

    const int t0tag = __ldg(&tagb[0]);
    float gold = trans_sh[t0tag * K_DIM + START_TAG] + fb[t0tag];

    // ---- depth-QD prefetch queue (clamped addresses; dead slots never consumed) ----
    float pf0[QD], pf1[QD], em[QD], gt[QD];
    {
        int ptag = t0tag;
#pragma unroll
        for (int s = 0; s < QD; s++) {
            int tp = s + 1; tp = (tp < len) ? tp : (len - 1);
            const float* ft = fb + tp * stride;
            pf0[s] = ft[j0];
            pf1[s] = has1 ? ft[j1] : 0.0f;
            const int tg = __ldg(&tagb[tp]);
            em[s] = ft[tg];
            gt[s] = trans_sh[tg * K_DIM + ptag];
            ptag = tg;
        }
        // carry running prefetch tag in em path below via shared var
    }
    int ptag_pf = __ldg(&tagb[(QD < len) ? QD : (len - 1)]);

    int t = 1;
    const int nquads = (len - 1) >> 2;
    const int rem = (len - 1) & 3;

    for (int q = 0; q < nquads; q++) {
#pragma unroll
        for (int s = 0; s < QD; s++) {
            // -------- consume slot s (step t) --------
            const float m = __shfl_sync(FULLMASK, alpha0, 0);
            const float a0 = __expf(alpha0 - m);
            const float a1 = __expf(alpha1 - m);

            float* buf = a_sh[warp][s & 1];
            buf[j0] = a0;
            if (has1) buf[j1] = a1;
            __syncwarp();

            float s0a = 0.f, s0b = 0.f, s1a = 0.f, s1b = 0.f;
            const float4* av = (const float4*)buf;
#pragma unroll
            for (int k = 0; k < K_DIM / 4; k++) {
                const float4 a = av[k];
                const int i = k * 4;
                s0a = fmaf(a.x, E0[i + 0], s0a);
                s0b = fmaf(a.y, E0[i + 1], s0b);
                s0a = fmaf(a.z, E0[i + 2], s0a);
                s0b = fmaf(a.w, E0[i + 3], s0b);
                s1a = fmaf(a.x, E1[i + 0], s1a);
                s1b = fmaf(a.y, E1[i + 1], s1b);
                s1a = fmaf(a.z, E1[i + 2], s1a);
                s1b = fmaf(a.w, E1[i + 3], s1b);
            }
            alpha0 = pf0[s] + m + __logf(s0a + s0b);
            alpha1 = pf1[s] + m + __logf(s1a + s1b);
            gold += gt[s] + em[s];

            // -------- refill slot s with step t+QD (clamped, branch-free) --------
            int tp = t + QD; tp = (tp < len) ? tp : (len - 1);
            const float* ft = fb + tp * stride;
            pf0[s] = ft[j0];
            pf1[s] = has1 ? ft[j1] : 0.0f;
            const int tg = __ldg(&tagb[tp]);
            em[s] = ft[tg];
            gt[s] = trans_sh[tg * K_DIM + ptag_pf];
            ptag_pf = tg;
            t++;
        }
    }

    // -------- remainder (0..3 steps), static slot indices --------
#pragma unroll
    for (int s = 0; s < 3; s++) {
        if (s < rem) {
            const float m = __shfl_sync(FULLMASK, alpha0, 0);
            const float a0 = __expf(alpha0 - m);
            const float a1 = __expf(alpha1 - m);

            float* buf = a_sh[warp][s & 1];
            __syncwarp();
            buf[j0] = a0;
            if (has1) buf[j1] = a1;
            __syncwarp();

            float s0a = 0.f, s0b = 0.f, s1a = 0.f, s1b = 0.f;
            const float4* av = (const float4*)buf;
#pragma unroll
            for (int k = 0; k < K_DIM / 4; k++) {
                const float4 a = av[k];
                const int i = k * 4;
                s0a = fmaf(a.x, E0[i + 0], s0a);
                s0b = fmaf(a.y, E0[i + 1], s0b);
                s0a = fmaf(a.z, E0[i + 2], s0a);
                s0b = fmaf(a.w, E0[i + 3], s0b);
                s1a = fmaf(a.x, E1[i + 0], s1a);
                s1b = fmaf(a.y, E1[i + 1], s1b);
                s1a = fmaf(a.z, E1[i + 2], s1a);
                s1b = fmaf(a.w, E1[i + 3], s1b);
            }
            alpha0 = pf0[s] + m + __logf(s0a + s0b);
            alpha1 = pf1[s] + m + __logf(s1a + s1b);
            gold += gt[s] + em[s];
        }
    }

    // ---- log_z = lse_j(alpha_j + trans[STOP, j]) ----
    float v0 = alpha0 + trans_sh[STOP_TAG * K_DIM + j0];
    float v1 = has1 ? (alpha1 + trans_sh[STOP_TAG * K_DIM + j1]) : -INFINITY;
    float mv = fmaxf(v0, v1);
#pragma unroll
    for (int off = 16; off > 0; off >>= 1)
        mv = fmaxf(mv, __shfl_xor_sync(FULLMASK, mv, off));
    float se = __expf(v0 - mv) + (has1 ? __expf(v1 - mv) : 0.0f);
#pragma unroll
    for (int off = 16; off > 0; off >>= 1)
        se += __shfl_xor_sync(FULLMASK, se, off);
    const float log_z = mv + __logf(se);

    const int lastTag = __ldg(&tagb[len - 1]);
    gold += trans_sh[STOP_TAG * K_DIM + lastTag];

    if (lane == 0) atomicAdd(out, log_z - gold);
}

extern "C" void kernel_launch(void* const* d_in, const int* in_sizes, int n_in,
                              void* d_out, int out_size) {
    const float* feats   = (const float*)d_in[0];
    const float* trans   = (const float*)d_in[1];
    const int*   tags    = (const int*)d_in[2];
    const int*   lengths = (const int*)d_in[3];
    float* out = (float*)d_out;

    crf_zero<<<1, 1>>>(out);
    crf_fwd<<<B_DIM / WPB, THREADS>>>(feats, trans, tags, lengths, out);
}